// round 8
// baseline (speedup 1.0000x reference)
#include <cuda_runtime.h>
#include <math_constants.h>
#include <cstdint>

#define POOL 7
#define NUM_ROIS 300
#define HH 50
#define WW 50
#define CC 512
#define NPIX (HH * WW)
#define NBINS (POOL * POOL)
#define TOTAL_BINS (NUM_ROIS * NBINS)       // 14700
#define BPB 4                               // bins per block (K1b and K2)
#define GRIDB (TOTAL_BINS / BPB)            // 3675
#define V4_PER_BIN (CC / 4)                 // 128 float4 per bin

// Scratch (no allocation): per-pixel channel max + per-bin pooled value.
__device__ float g_fmax[NPIX];
__device__ float g_bin[TOTAL_BINS];

// ---------------- K1: channel max per pixel (warp per pixel) ----------------
__global__ void fmax_kernel(const float* __restrict__ fm) {
    int gwarp = (blockIdx.x * blockDim.x + threadIdx.x) >> 5;
    int lane  = threadIdx.x & 31;
    if (gwarp < NPIX) {
        const float4* p = reinterpret_cast<const float4*>(fm + (size_t)gwarp * CC);
        float m = -CUDART_INF_F;
#pragma unroll
        for (int i = 0; i < 4; i++) {
            float4 v = p[lane + i * 32];
            m = fmaxf(m, fmaxf(fmaxf(v.x, v.y), fmaxf(v.z, v.w)));
        }
#pragma unroll
        for (int s = 16; s; s >>= 1)
            m = fmaxf(m, __shfl_xor_sync(0xffffffffu, m, s));
        if (lane == 0) g_fmax[gwarp] = m;
    }
    cudaTriggerProgrammaticLaunchCompletion();
}

// ---------------- K1b: one warp per bin -> g_bin ----------------
__global__ void __launch_bounds__(128) bin_kernel(const float* __restrict__ rois) {
    int wid  = threadIdx.x >> 5;
    int lane = threadIdx.x & 31;
    int g    = blockIdx.x * BPB + wid;      // global bin id
    int roi  = g / NBINS;                   // const divisors -> mul/shift
    int bin  = g - roi * NBINS;
    int bi   = bin / POOL;
    int bj   = bin - bi * POOL;

    // Setup from rois (input buffer, independent of K1) BEFORE grid sync.
    const float inv = 1.0f / 16.0f;
    int x1 = (int)(rois[roi * 5 + 1] * inv);
    int y1 = (int)(rois[roi * 5 + 2] * inv);
    int x2 = (int)(rois[roi * 5 + 3] * inv);
    int y2 = (int)(rois[roi * 5 + 4] * inv);
    int rh = y2 - y1 + 1;
    int rw = x2 - x1 + 1;

    int hs = min(max(y1 + (bi * rh) / POOL, 0), HH);
    int he = min(max(y1 + ((bi + 1) * rh + POOL - 1) / POOL, 0), HH);
    int ws = min(max(x1 + (bj * rw) / POOL, 0), WW);
    int we = min(max(x1 + ((bj + 1) * rw + POOL - 1) / POOL, 0), WW);

    int nh = he - hs;
    int nw = we - ws;
    int n  = (nh > 0 && nw > 0) ? nh * nw : 0;   // <= 64 cells (bin <= 8x8)

    cudaGridDependencySynchronize();             // wait for g_fmax

    float m = -CUDART_INF_F;
    for (int idx = lane; idx < n; idx += 32) {   // <= 2 iters
        int r = idx / nw;
        int c = idx - r * nw;
        m = fmaxf(m, g_fmax[(hs + r) * WW + (ws + c)]);
    }
#pragma unroll
    for (int s = 16; s; s >>= 1)
        m = fmaxf(m, __shfl_xor_sync(0xffffffffu, m, s));
    if (lane == 0) g_bin[g] = m;

    cudaTriggerProgrammaticLaunchCompletion();
}

// ---------------- K2: pure broadcast streamer ----------------
// No sync, no shfl: 4 uniform loads + 4 STG.128 per thread.
__global__ void __launch_bounds__(128) stream_kernel(float* __restrict__ out) {
    int tid = threadIdx.x;
    int b   = blockIdx.x;
    float4* out4 = reinterpret_cast<float4*>(out) + (size_t)b * (BPB * V4_PER_BIN);

    cudaGridDependencySynchronize();             // wait for g_bin

    float v0 = g_bin[b * BPB + 0];
    float v1 = g_bin[b * BPB + 1];
    float v2 = g_bin[b * BPB + 2];
    float v3 = g_bin[b * BPB + 3];

    out4[tid            ] = make_float4(v0, v0, v0, v0);
    out4[tid + 128      ] = make_float4(v1, v1, v1, v1);
    out4[tid + 256      ] = make_float4(v2, v2, v2, v2);
    out4[tid + 384      ] = make_float4(v3, v3, v3, v3);
}

extern "C" void kernel_launch(void* const* d_in, const int* in_sizes, int n_in,
                              void* d_out, int out_size) {
    const float* rois = (const float*)d_in[0];
    const float* fm   = (const float*)d_in[1];
    if (in_sizes[0] != NUM_ROIS * 5) {
        const float* t = rois; rois = fm; fm = t;
    }
    float* out = (float*)d_out;

    int threads1 = 256;
    int blocks1  = (NPIX * 32 + threads1 - 1) / threads1;
    fmax_kernel<<<blocks1, threads1>>>(fm);

    cudaLaunchAttribute attrs[1];
    attrs[0].id = cudaLaunchAttributeProgrammaticStreamSerialization;
    attrs[0].val.programmaticStreamSerializationAllowed = 1;

    cudaLaunchConfig_t cfg = {};
    cfg.blockDim = dim3(128, 1, 1);
    cfg.stream   = 0;
    cfg.attrs    = attrs;
    cfg.numAttrs = 1;

    cfg.gridDim = dim3(GRIDB, 1, 1);
    cudaLaunchKernelEx(&cfg, bin_kernel, rois);

    cfg.gridDim = dim3(GRIDB, 1, 1);
    cudaLaunchKernelEx(&cfg, stream_kernel, out);
}

// round 9
// speedup vs baseline: 1.1830x; 1.1830x over previous
#include <cuda_runtime.h>
#include <math_constants.h>
#include <cstdint>

#define POOL 7
#define NUM_ROIS 300
#define HH 50
#define WW 50
#define CC 512
#define NPIX (HH * WW)
#define NBINS (POOL * POOL)
#define TOTAL_BINS (NUM_ROIS * NBINS)        // 14700
#define V4_PER_BIN (CC / 4)                  // 128 float4 per bin
#define TOTAL_V4 ((size_t)TOTAL_BINS * V4_PER_BIN)
#define BPB 8                                // bins per group (one warp each)
#define GROUPS ((TOTAL_BINS + BPB - 1) / BPB) // 1838 (last group partial)
#define GRID2 919
#define ITERS 2

// Scratch: channel-max per pixel (10 KB). __device__ global (no allocation).
__device__ float g_fmax[NPIX];

// ---------------- K1: channel max per pixel (warp per pixel) ----------------
__global__ void fmax_kernel(const float* __restrict__ fm) {
    int gwarp = (blockIdx.x * blockDim.x + threadIdx.x) >> 5;
    int lane  = threadIdx.x & 31;
    if (gwarp < NPIX) {
        const float4* p = reinterpret_cast<const float4*>(fm + (size_t)gwarp * CC);
        float m = -CUDART_INF_F;
#pragma unroll
        for (int i = 0; i < 4; i++) {
            float4 v = p[lane + i * 32];
            m = fmaxf(m, fmaxf(fmaxf(v.x, v.y), fmaxf(v.z, v.w)));
        }
#pragma unroll
        for (int s = 16; s; s >>= 1)
            m = fmaxf(m, __shfl_xor_sync(0xffffffffu, m, s));
        if (lane == 0) g_fmax[gwarp] = m;
    }
    cudaTriggerProgrammaticLaunchCompletion();
}

// ---------------- K2: reduce + broadcast streamer, 2 groups per block ------
// Prologue (rois + window math for BOTH groups) runs before the grid sync so
// it overlaps K1's tail under PDL. Post-sync chain is only fmax-load + shfl.
// Double-buffered s_bin so group 1's reduce overlaps group 0's store drain.
__global__ void __launch_bounds__(256) stream2_kernel(
    const float* __restrict__ rois, float* __restrict__ out) {
    __shared__ float s_bin[ITERS][BPB];

    int tid  = threadIdx.x;
    int wid  = tid >> 5;
    int lane = tid & 31;
    const float inv = 1.0f / 16.0f;

    int hs[ITERS], hev[ITERS], ws[ITERS], wev[ITERS];
    bool valid[ITERS];

#pragma unroll
    for (int it = 0; it < ITERS; it++) {
        int grp = blockIdx.x + it * GRID2;
        int g   = grp * BPB + wid;
        valid[it] = (g < TOTAL_BINS);
        int gc  = valid[it] ? g : 0;
        int roi = gc / NBINS;
        int bin = gc - roi * NBINS;
        int bi  = bin / POOL;
        int bj  = bin - bi * POOL;

        int x1 = (int)(rois[roi * 5 + 1] * inv);
        int y1 = (int)(rois[roi * 5 + 2] * inv);
        int x2 = (int)(rois[roi * 5 + 3] * inv);
        int y2 = (int)(rois[roi * 5 + 4] * inv);
        int rh = y2 - y1 + 1;
        int rw = x2 - x1 + 1;

        hs[it]  = min(max(y1 + (bi * rh) / POOL, 0), HH);
        hev[it] = min(max(y1 + ((bi + 1) * rh + POOL - 1) / POOL, 0), HH);
        ws[it]  = min(max(x1 + (bj * rw) / POOL, 0), WW);
        wev[it] = min(max(x1 + ((bj + 1) * rw + POOL - 1) / POOL, 0), WW);
    }

    // Wait for K1's g_fmax (PDL). Everything above overlapped K1.
    cudaGridDependencySynchronize();

#pragma unroll
    for (int it = 0; it < ITERS; it++) {
        // ---- reduce: one warp per bin ----
        int nh = hev[it] - hs[it];
        int nw = wev[it] - ws[it];
        int n  = (nh > 0 && nw > 0) ? nh * nw : 0;     // <= 64 cells
        float m = -CUDART_INF_F;
        for (int idx = lane; idx < n; idx += 32) {     // <= 2 iters
            int r = idx / nw;
            int c = idx - r * nw;
            m = fmaxf(m, g_fmax[(hs[it] + r) * WW + (ws[it] + c)]);
        }
#pragma unroll
        for (int s = 16; s; s >>= 1)
            m = fmaxf(m, __shfl_xor_sync(0xffffffffu, m, s));
        if (lane == 0) s_bin[it][wid] = m;
        __syncthreads();

        // ---- stream 16KB (1024 float4): 4 STG.128 per thread ----
        int grp = blockIdx.x + it * GRID2;
        size_t base = (size_t)grp * (BPB * V4_PER_BIN);
        float4* o = reinterpret_cast<float4*>(out) + base;
        if (base + BPB * V4_PER_BIN <= TOTAL_V4) {     // full group (fast path)
#pragma unroll
            for (int k = 0; k < 4; k++) {
                int i = tid + k * 256;
                float v = s_bin[it][i >> 7];
                o[i] = make_float4(v, v, v, v);
            }
        } else {                                       // last partial group
#pragma unroll
            for (int k = 0; k < 4; k++) {
                int i = tid + k * 256;
                if (base + i < TOTAL_V4) {
                    float v = s_bin[it][i >> 7];
                    o[i] = make_float4(v, v, v, v);
                }
            }
        }
        // no trailing sync: next iter writes the other s_bin buffer
    }
}

extern "C" void kernel_launch(void* const* d_in, const int* in_sizes, int n_in,
                              void* d_out, int out_size) {
    const float* rois = (const float*)d_in[0];
    const float* fm   = (const float*)d_in[1];
    if (in_sizes[0] != NUM_ROIS * 5) {
        const float* t = rois; rois = fm; fm = t;
    }
    float* out = (float*)d_out;

    int threads1 = 256;
    int blocks1  = (NPIX * 32 + threads1 - 1) / threads1;
    fmax_kernel<<<blocks1, threads1>>>(fm);

    cudaLaunchAttribute attrs[1];
    attrs[0].id = cudaLaunchAttributeProgrammaticStreamSerialization;
    attrs[0].val.programmaticStreamSerializationAllowed = 1;

    cudaLaunchConfig_t cfg = {};
    cfg.gridDim  = dim3(GRID2, 1, 1);
    cfg.blockDim = dim3(256, 1, 1);
    cfg.stream   = 0;
    cfg.attrs    = attrs;
    cfg.numAttrs = 1;

    cudaLaunchKernelEx(&cfg, stream2_kernel, rois, out);
}

// round 11
// speedup vs baseline: 1.4090x; 1.1910x over previous
#include <cuda_runtime.h>
#include <math_constants.h>
#include <cstdint>

#define POOL 7
#define NUM_ROIS 300
#define HH 50
#define WW 50
#define CC 512
#define NPIX (HH * WW)
#define NBINS (POOL * POOL)
#define TOTAL_BINS (NUM_ROIS * NBINS)        // 14700
#define V4_PER_BIN (CC / 4)                  // 128 float4 per bin
#define WPB 8                                // warps per block
#define GRID2 ((TOTAL_BINS + WPB - 1) / WPB) // 1838

// Scratch: channel-max per pixel (10 KB). __device__ global (no allocation).
__device__ float g_fmax[NPIX];

// ---------------- K1: channel max per pixel (warp per pixel) ----------------
__global__ void fmax_kernel(const float* __restrict__ fm) {
    int gwarp = (blockIdx.x * blockDim.x + threadIdx.x) >> 5;
    int lane  = threadIdx.x & 31;
    if (gwarp < NPIX) {
        const float4* p = reinterpret_cast<const float4*>(fm + (size_t)gwarp * CC);
        float m = -CUDART_INF_F;
#pragma unroll
        for (int i = 0; i < 4; i++) {
            float4 v = p[lane + i * 32];
            m = fmaxf(m, fmaxf(fmaxf(v.x, v.y), fmaxf(v.z, v.w)));
        }
#pragma unroll
        for (int s = 16; s; s >>= 1)
            m = fmaxf(m, __shfl_xor_sync(0xffffffffu, m, s));
        if (lane == 0) g_fmax[gwarp] = m;
    }
    cudaTriggerProgrammaticLaunchCompletion();
}

// ---------------- K2: one warp per bin, zero smem / zero barriers ----------
// Butterfly reduce leaves the bin max in every lane; each warp then streams
// its own 2KB of broadcast output as 4 independent streaming STG.128/lane.
__global__ void __launch_bounds__(WPB * 32) stream_warp_kernel(
    const float* __restrict__ rois, float* __restrict__ out) {
    int tid  = threadIdx.x;
    int lane = tid & 31;
    int g    = blockIdx.x * WPB + (tid >> 5);   // global bin id
    bool act = (g < TOTAL_BINS);
    int gc   = act ? g : 0;

    // ---- Prologue (overlaps K1 tail under PDL): window math from rois ----
    int roi = gc / NBINS;
    int bin = gc - roi * NBINS;
    int bi  = bin / POOL;
    int bj  = bin - bi * POOL;

    const float inv = 1.0f / 16.0f;
    int x1 = (int)(rois[roi * 5 + 1] * inv);
    int y1 = (int)(rois[roi * 5 + 2] * inv);
    int x2 = (int)(rois[roi * 5 + 3] * inv);
    int y2 = (int)(rois[roi * 5 + 4] * inv);
    int rh = y2 - y1 + 1;
    int rw = x2 - x1 + 1;

    int hs = min(max(y1 + (bi * rh) / POOL, 0), HH);
    int he = min(max(y1 + ((bi + 1) * rh + POOL - 1) / POOL, 0), HH);
    int ws = min(max(x1 + (bj * rw) / POOL, 0), WW);
    int we = min(max(x1 + ((bj + 1) * rw + POOL - 1) / POOL, 0), WW);

    int nh = he - hs;
    int nw = we - ws;
    int n  = (nh > 0 && nw > 0) ? nh * nw : 0;  // <= 64 cells

    cudaGridDependencySynchronize();            // wait for g_fmax

    // ---- Reduce: <=2 L2-hot loads per lane + butterfly ----
    float m = -CUDART_INF_F;
    for (int idx = lane; idx < n; idx += 32) {
        int r = idx / nw;
        int c = idx - r * nw;
        m = fmaxf(m, g_fmax[(hs + r) * WW + (ws + c)]);
    }
#pragma unroll
    for (int s = 16; s; s >>= 1)
        m = fmaxf(m, __shfl_xor_sync(0xffffffffu, m, s));
    // every lane now holds the bin max

    // ---- Stream this bin's 2KB: 4 independent streaming STG.128 per lane --
    if (act) {
        float4* o = reinterpret_cast<float4*>(out) + (size_t)g * V4_PER_BIN;
        float4 v4 = make_float4(m, m, m, m);
        __stcs(o + lane,      v4);
        __stcs(o + lane + 32, v4);
        __stcs(o + lane + 64, v4);
        __stcs(o + lane + 96, v4);
    }
}

extern "C" void kernel_launch(void* const* d_in, const int* in_sizes, int n_in,
                              void* d_out, int out_size) {
    const float* rois = (const float*)d_in[0];
    const float* fm   = (const float*)d_in[1];
    if (in_sizes[0] != NUM_ROIS * 5) {
        const float* t = rois; rois = fm; fm = t;
    }
    float* out = (float*)d_out;

    int threads1 = 256;
    int blocks1  = (NPIX * 32 + threads1 - 1) / threads1;
    fmax_kernel<<<blocks1, threads1>>>(fm);

    cudaLaunchAttribute attrs[1];
    attrs[0].id = cudaLaunchAttributeProgrammaticStreamSerialization;
    attrs[0].val.programmaticStreamSerializationAllowed = 1;

    cudaLaunchConfig_t cfg = {};
    cfg.gridDim  = dim3(GRID2, 1, 1);
    cfg.blockDim = dim3(WPB * 32, 1, 1);
    cfg.stream   = 0;
    cfg.attrs    = attrs;
    cfg.numAttrs = 1;

    cudaLaunchKernelEx(&cfg, stream_warp_kernel, rois, out);
}